// round 5
// baseline (speedup 1.0000x reference)
#include <cuda_runtime.h>
#include <cstdint>
#include <cstddef>

// ---------------- problem geometry ----------------
#define IN_W   512
#define IN_H   512
#define OUT_W  1024
#define OUT_H  1024
#define NB     32
#define NC     3

#define TX     128
#define TY     32
#define ITR    24          // input tile rows  (TY/2 + 8)
#define ITC    72          // input tile cols  (TX/2 + 8)

typedef unsigned long long ull;

// ---------------- compile-time Lanczos4 weights (2 phases) ----------------
struct W16 { float w0[8]; float w1[8]; };

constexpr W16 make_weights() {
    const double sq  = 0.70710678118654752440;
    const double s1  = 0.19509032201612826785;
    const double s3  = 0.55557023301960222474;
    const double s5  = 0.83146961230254523708;
    const double s7  = 0.98078528040323044913;
    const double pi  = 3.14159265358979323846;
    const double d[8]    = { 3.75,  2.75,  1.75,  0.75, -0.25, -1.25, -2.25, -3.25 };
    const double spd[8]  = { -sq ,  sq  , -sq  ,  sq  , -sq  ,  sq  , -sq  ,  sq   };
    const double spd4[8] = {  s1 ,  s5  ,  s7  ,  s3  , -s1  , -s5  , -s7  , -s3   };
    double raw[8] = {};
    double s = 0.0;
    for (int t = 0; t < 8; ++t) {
        raw[t] = spd[t] * spd4[t] * 4.0 / (pi * pi * d[t] * d[t]);
        s += raw[t];
    }
    W16 r{};
    for (int t = 0; t < 8; ++t) {
        r.w0[t]     = (float)(raw[t] / s);  // phase 0.75 (even outputs)
        r.w1[7 - t] = (float)(raw[t] / s);  // phase 0.25 (odd)  = mirror
    }
    return r;
}
constexpr W16 KW = make_weights();

// ---------------- f32x2 packed-math helpers ----------------
__device__ __forceinline__ ull pk2(float lo, float hi) {
    ull r; asm("mov.b64 %0, {%1, %2};" : "=l"(r) : "f"(lo), "f"(hi)); return r;
}
__device__ __forceinline__ float2 upk2(ull v) {
    float2 r; asm("mov.b64 {%0, %1}, %2;" : "=f"(r.x), "=f"(r.y) : "l"(v)); return r;
}
__device__ __forceinline__ void fma2(ull& acc, ull a, ull b) {
    asm("fma.rn.f32x2 %0, %1, %2, %0;" : "+l"(acc) : "l"(a), "l"(b));
}
__device__ __forceinline__ ull fma2n(ull a, ull b, ull c) {
    ull r; asm("fma.rn.f32x2 %0, %1, %2, %3;" : "=l"(r) : "l"(a), "l"(b), "l"(c)); return r;
}
__device__ __forceinline__ ull mul2(ull a, ull b) {
    ull r; asm("mul.rn.f32x2 %0, %1, %2;" : "=l"(r) : "l"(a), "l"(b)); return r;
}

// ---------------- per-image min/max scratch ----------------
__device__ unsigned g_minenc[NB];
__device__ unsigned g_maxenc[NB];

__device__ __forceinline__ unsigned encf(float f) {
    unsigned u = __float_as_uint(f);
    return (u & 0x80000000u) ? ~u : (u | 0x80000000u);
}
__device__ __forceinline__ float decf(unsigned e) {
    return (e & 0x80000000u) ? __uint_as_float(e & 0x7FFFFFFFu) : __uint_as_float(~e);
}

__global__ void k_init_minmax() {
    unsigned i = threadIdx.x;
    if (i < NB) { g_minenc[i] = 0xFFFFFFFFu; g_maxenc[i] = 0u; }
}

// ---------------- main resize kernel ----------------
// PASS 0: resize tile, reduce per-image min/max (no stores).
// PASS 1: resize tile, renormalize, store float32 (uint8-valued).
template <int PASS>
__global__ void __launch_bounds__(256, 3)
k_resize(const float* __restrict__ x, float* __restrict__ out)
{
    __shared__ __align__(16) float s_in[ITR * ITC];   // input tile (replicate-padded)
    __shared__ __align__(16) float s_it[TY * ITC];    // H-resampled intermediate
    __shared__ float red[16];

    const int tid = threadIdx.x;
    const int bc  = blockIdx.z;
    const int img = bc / 3;
    const int ox0 = blockIdx.x * TX;
    const int oy0 = blockIdx.y * TY;
    const int ix0 = (ox0 >> 1) - 4;
    const int iy0 = (oy0 >> 1) - 4;
    const float* __restrict__ src = x + (size_t)bc * (IN_W * IN_H);

    // local scalar weights (compile-time constants after unroll)
    const float w0[8] = { KW.w0[0], KW.w0[1], KW.w0[2], KW.w0[3],
                          KW.w0[4], KW.w0[5], KW.w0[6], KW.w0[7] };
    const float w1[8] = { KW.w1[0], KW.w1[1], KW.w1[2], KW.w1[3],
                          KW.w1[4], KW.w1[5], KW.w1[6], KW.w1[7] };

    // ---- load input tile (replicate border via clamped index) ----
    for (int e = tid; e < ITR * ITC; e += 256) {
        int r = e / ITC;
        int c = e - r * ITC;
        int gy = min(max(iy0 + r, 0), IN_H - 1);
        int gx = min(max(ix0 + c, 0), IN_W - 1);
        s_in[e] = __ldg(src + gy * IN_W + gx);
    }
    __syncthreads();

    // ---- H (vertical) resample: unit = (column pair, rowgroup of 8 out rows) ----
    // 36 col-pairs x 4 rowgroups = 144 units. f32x2 lanes = two adjacent columns.
    if (tid < 144) {
        const int cp = tid % 36;          // column pair: cols 2cp, 2cp+1
        const int rg = tid / 36;          // output rows rg*8 .. rg*8+7
        const ull* b = reinterpret_cast<const ull*>(s_in) + (rg * 4) * (ITC / 2) + cp;
        ull v[12];
#pragma unroll
        for (int k = 0; k < 12; ++k) v[k] = b[k * (ITC / 2)];

        ull WB[8];                         // broadcast (w0[t], w0[t]); w1[t] = w0[7-t]
#pragma unroll
        for (int t = 0; t < 8; ++t) WB[t] = pk2(w0[t], w0[t]);

        ull* o = reinterpret_cast<ull*>(s_it) + (rg * 8) * (ITC / 2) + cp;
#pragma unroll
        for (int j = 0; j < 8; ++j) {
            const int off = (j + (j & 1)) >> 1;
            ull acc = 0ull;
#pragma unroll
            for (int t = 0; t < 8; ++t)
                fma2(acc, v[off + t], (j & 1) ? WB[7 - t] : WB[t]);
            o[j * (ITC / 2)] = acc;
        }
    }
    __syncthreads();

    // ---- W (horizontal) resample: unit = (row, 8 output cols), 512 units ----
    float lmin = 3.0e38f, lmax = -3.0e38f;

    // pass-1 renorm constants: y = clamp(min_or_max(C*im, D*im+E))
    float Cc = 255.0f, D1 = 255.0f, E1 = 0.0f;
    bool fast = true;
    if (PASS == 1) {
        float mn = decf(g_minenc[img]);
        float mx = decf(g_maxenc[img]);
        if ((mx - mn) > 1.0f) {
            const float ott = 1.0f / 255.0f, ubt = -10.0f / 255.0f;
            const float c = 1.0f - ott, d = 1.0f - ubt;
            float otr = mx - 1.0f;
            float a1  = ott / (otr != 0.0f ? otr : 1.0f);
            Cc = 255.0f * c * d;
            D1 = 255.0f * d * a1;
            E1 = Cc - D1;                   // continuity at im = 1
            fast = (D1 <= Cc);              // min-composition valid
        }
    }
    const ull C2 = pk2(Cc, Cc), D2 = pk2(D1, D1), E2 = pk2(E1, E1);

    ull WV[8];                              // (w0[t], w1[t]) pairs
#pragma unroll
    for (int t = 0; t < 8; ++t) WV[t] = pk2(w0[t], w1[t]);

#pragma unroll
    for (int it = 0; it < 2; ++it) {
        const int u = tid + it * 256;
        const int h = u & 15;               // output cols 8h..8h+7
        const int r = u >> 4;               // output row (tile-local)

        const float4* p = reinterpret_cast<const float4*>(s_it + r * ITC + 4 * h);
        const float4 qa = p[0], qb = p[1], qc = p[2];
        const float v0 = qa.x, v1 = qa.y, v2 = qa.z, v3 = qa.w;
        const float v4 = qb.x, v5 = qb.y, v6 = qb.z, v7 = qb.w;
        const float v8 = qc.x, v9 = qc.y, v10 = qc.z, v11 = qc.w;

        ull P[11];
        P[0] = pk2(v0, v1);  P[1] = pk2(v1, v2);  P[2] = pk2(v2, v3);
        P[3] = pk2(v3, v4);  P[4] = pk2(v4, v5);  P[5] = pk2(v5, v6);
        P[6] = pk2(v6, v7);  P[7] = pk2(v7, v8);  P[8] = pk2(v8, v9);
        P[9] = pk2(v9, v10); P[10] = pk2(v10, v11);

        ull a01 = 0ull, a23 = 0ull, a45 = 0ull, a67 = 0ull;
#pragma unroll
        for (int t = 0; t < 8; ++t) {
            fma2(a01, P[t],     WV[t]);
            fma2(a23, P[t + 1], WV[t]);
            fma2(a45, P[t + 2], WV[t]);
            fma2(a67, P[t + 3], WV[t]);
        }

        if (PASS == 0) {
            float2 f0 = upk2(a01), f1 = upk2(a23), f2 = upk2(a45), f3 = upk2(a67);
            float mn0 = fminf(fminf(f0.x, f0.y), fminf(f1.x, f1.y));
            float mn1 = fminf(fminf(f2.x, f2.y), fminf(f3.x, f3.y));
            float mx0 = fmaxf(fmaxf(f0.x, f0.y), fmaxf(f1.x, f1.y));
            float mx1 = fmaxf(fmaxf(f2.x, f2.y), fmaxf(f3.x, f3.y));
            lmin = fminf(lmin, fminf(mn0, mn1));
            lmax = fmaxf(lmax, fmaxf(mx0, mx1));
        } else {
            float res[8];
#pragma unroll
            for (int q = 0; q < 4; ++q) {
                const ull acc = (q == 0) ? a01 : (q == 1) ? a23 : (q == 2) ? a45 : a67;
                ull m1 = mul2(acc, C2);
                ull m2 = fma2n(acc, D2, E2);
                float2 u1 = upk2(m1), u2 = upk2(m2);
                float ya = fast ? fminf(u1.x, u2.x) : fmaxf(u1.x, u2.x);
                float yb = fast ? fminf(u1.y, u2.y) : fmaxf(u1.y, u2.y);
                res[2 * q]     = (float)min(__float2uint_rz(ya), 255u);
                res[2 * q + 1] = (float)min(__float2uint_rz(yb), 255u);
            }
            float4 q1 = { res[0], res[1], res[2], res[3] };
            float4 q2 = { res[4], res[5], res[6], res[7] };
            size_t o = (size_t)bc * (OUT_H * OUT_W)
                     + (size_t)(oy0 + r) * OUT_W + ox0 + 8 * h;
            *reinterpret_cast<float4*>(out + o)     = q1;
            *reinterpret_cast<float4*>(out + o + 4) = q2;
        }
    }

    if (PASS == 0) {
#pragma unroll
        for (int o = 16; o; o >>= 1) {
            lmin = fminf(lmin, __shfl_xor_sync(0xFFFFFFFFu, lmin, o));
            lmax = fmaxf(lmax, __shfl_xor_sync(0xFFFFFFFFu, lmax, o));
        }
        const int wid = tid >> 5;
        if ((tid & 31) == 0) { red[wid] = lmin; red[8 + wid] = lmax; }
        __syncthreads();
        if (tid == 0) {
            float m0 = red[0], m1 = red[8];
#pragma unroll
            for (int i = 1; i < 8; ++i) {
                m0 = fminf(m0, red[i]);
                m1 = fmaxf(m1, red[8 + i]);
            }
            atomicMin(&g_minenc[img], encf(m0));
            atomicMax(&g_maxenc[img], encf(m1));
        }
    }
}

extern "C" void kernel_launch(void* const* d_in, const int* in_sizes, int n_in,
                              void* d_out, int out_size) {
    const float* x = (const float*)d_in[0];
    float* out = (float*)d_out;

    dim3 grid(OUT_W / TX, OUT_H / TY, NB * NC);   // 8 x 32 x 96
    k_init_minmax<<<1, 32>>>();
    k_resize<0><<<grid, 256>>>(x, nullptr);       // resize + per-image min/max
    k_resize<1><<<grid, 256>>>(x, out);           // resize + renorm + f32(u8) store
}

// round 6
// speedup vs baseline: 1.5190x; 1.5190x over previous
#include <cuda_runtime.h>
#include <cstdint>
#include <cstddef>

// ---------------- problem geometry ----------------
#define IN_W   512
#define IN_H   512
#define OUT_W  1024
#define OUT_H  1024
#define NB     32
#define NC     3

#define TX     128
#define TY     32
#define ITR    24          // input tile rows  (TY/2 + 8)
#define ITC    72          // input tile cols  (TX/2 + 8)
#define NTILES (8 * 32 * NB * NC)   // 24576 CTAs in resize grid
#define TILES_PER_IMG (8 * 32 * NC) // 768

// ---------------- compile-time Lanczos4 weights (2 phases) ----------------
struct W16 { float w0[8]; float w1[8]; };

constexpr W16 make_weights() {
    const double sq  = 0.70710678118654752440;
    const double s1  = 0.19509032201612826785;
    const double s3  = 0.55557023301960222474;
    const double s5  = 0.83146961230254523708;
    const double s7  = 0.98078528040323044913;
    const double pi  = 3.14159265358979323846;
    const double d[8]    = { 3.75,  2.75,  1.75,  0.75, -0.25, -1.25, -2.25, -3.25 };
    const double spd[8]  = { -sq ,  sq  , -sq  ,  sq  , -sq  ,  sq  , -sq  ,  sq   };
    const double spd4[8] = {  s1 ,  s5  ,  s7  ,  s3  , -s1  , -s5  , -s7  , -s3   };
    double raw[8] = {};
    double s = 0.0;
    for (int t = 0; t < 8; ++t) {
        raw[t] = spd[t] * spd4[t] * 4.0 / (pi * pi * d[t] * d[t]);
        s += raw[t];
    }
    W16 r{};
    for (int t = 0; t < 8; ++t) {
        r.w0[t]     = (float)(raw[t] / s);  // phase 0.75 (even outputs)
        r.w1[7 - t] = (float)(raw[t] / s);  // phase 0.25 (odd) = mirror
    }
    return r;
}
constexpr W16 KW = make_weights();

// ---------------- min/max scratch (written every call; no init needed) ----
__device__ float g_pmin[NTILES];
__device__ float g_pmax[NTILES];
__device__ float g_min[NB];
__device__ float g_max[NB];

// ---------------- reduce kernel: per-image min/max from tile partials ------
__global__ void __launch_bounds__(256) k_reduce() {
    const int img  = blockIdx.x;
    const int base = img * TILES_PER_IMG;
    const int tid  = threadIdx.x;
    float mn = 3.0e38f, mx = -3.0e38f;
    for (int i = tid; i < TILES_PER_IMG; i += 256) {
        mn = fminf(mn, g_pmin[base + i]);
        mx = fmaxf(mx, g_pmax[base + i]);
    }
#pragma unroll
    for (int o = 16; o; o >>= 1) {
        mn = fminf(mn, __shfl_xor_sync(0xFFFFFFFFu, mn, o));
        mx = fmaxf(mx, __shfl_xor_sync(0xFFFFFFFFu, mx, o));
    }
    __shared__ float red[16];
    const int wid = tid >> 5;
    if ((tid & 31) == 0) { red[wid] = mn; red[8 + wid] = mx; }
    __syncthreads();
    if (tid == 0) {
        float m0 = red[0], m1 = red[8];
#pragma unroll
        for (int i = 1; i < 8; ++i) {
            m0 = fminf(m0, red[i]);
            m1 = fmaxf(m1, red[8 + i]);
        }
        g_min[img] = m0;
        g_max[img] = m1;
    }
}

// ---------------- main resize kernel ----------------
// PASS 0: resize tile -> per-tile min/max into scratch (no image stores).
// PASS 1: resize tile -> renormalize -> store float32 (uint8-valued).
template <int PASS>
__global__ void __launch_bounds__(256, 4)
k_resize(const float* __restrict__ x, float* __restrict__ out)
{
    __shared__ __align__(16) float s_in[ITR * ITC];   // input tile
    __shared__ __align__(16) float s_it[TY * ITC];    // H-resampled intermediate

    const int tid = threadIdx.x;
    const int bc  = blockIdx.z;
    const int img = bc / 3;
    const int ox0 = blockIdx.x * TX;
    const int oy0 = blockIdx.y * TY;
    const int ix0 = (ox0 >> 1) - 4;
    const int iy0 = (oy0 >> 1) - 4;
    const float* __restrict__ src = x + (size_t)bc * (IN_W * IN_H);

    const float w0[8] = { KW.w0[0], KW.w0[1], KW.w0[2], KW.w0[3],
                          KW.w0[4], KW.w0[5], KW.w0[6], KW.w0[7] };
    const float w1[8] = { KW.w1[0], KW.w1[1], KW.w1[2], KW.w1[3],
                          KW.w1[4], KW.w1[5], KW.w1[6], KW.w1[7] };

    // ---- load input tile ----
    const bool interior = (ix0 >= 0) & (ix0 + ITC <= IN_W) &
                          (iy0 >= 0) & (iy0 + ITR <= IN_H);
    if (interior) {
        // 24 rows x 18 float4 = 432 vector loads, 16B-aligned (ix0 = 64bx-4)
        const float4* s4 = reinterpret_cast<const float4*>(src + (size_t)iy0 * IN_W + ix0);
        float4* d4 = reinterpret_cast<float4*>(s_in);
#pragma unroll
        for (int it = 0; it < 2; ++it) {
            int e = tid + it * 256;
            if (e < 432) {
                int r = e / 18;
                int c = e - r * 18;
                d4[e] = __ldg(s4 + (size_t)r * (IN_W / 4) + c);
            }
        }
    } else {
        for (int e = tid; e < ITR * ITC; e += 256) {
            int r = e / ITC;
            int c = e - r * ITC;
            int gy = min(max(iy0 + r, 0), IN_H - 1);
            int gx = min(max(ix0 + c, 0), IN_W - 1);
            s_in[e] = __ldg(src + gy * IN_W + gx);
        }
    }
    __syncthreads();

    // ---- H (vertical) resample: unit = (col, 4 output rows); 72*8 = 576 units
    for (int u = tid; u < ITC * 8; u += 256) {
        const int rg = u / ITC;           // output rows 4rg..4rg+3
        const int c  = u - rg * ITC;
        float v[10];
#pragma unroll
        for (int k = 0; k < 10; ++k)
            v[k] = s_in[(2 * rg + k) * ITC + c];
        float o0 = 0.f, o1 = 0.f, o2 = 0.f, o3 = 0.f;
#pragma unroll
        for (int t = 0; t < 8; ++t) {
            o0 = fmaf(w0[t], v[t],     o0);   // row 4rg   (even)
            o1 = fmaf(w1[t], v[t + 1], o1);   // row 4rg+1 (odd)
            o2 = fmaf(w0[t], v[t + 1], o2);   // row 4rg+2 (even)
            o3 = fmaf(w1[t], v[t + 2], o3);   // row 4rg+3 (odd)
        }
        float* o = s_it + (4 * rg) * ITC + c;
        o[0 * ITC] = o0;  o[1 * ITC] = o1;
        o[2 * ITC] = o2;  o[3 * ITC] = o3;
    }
    __syncthreads();

    // ---- pass-1 renorm constants: y = min_or_max(C*im, D*im + E) ----
    float Cc = 255.0f, D1 = 255.0f, E1 = 0.0f;
    bool fast = true;
    if (PASS == 1) {
        float mn = g_min[img];
        float mx = g_max[img];
        if ((mx - mn) > 1.0f) {
            const float ott = 1.0f / 255.0f, ubt = -10.0f / 255.0f;
            const float c = 1.0f - ott, d = 1.0f - ubt;
            float otr = mx - 1.0f;
            float a1  = ott / (otr != 0.0f ? otr : 1.0f);
            Cc = 255.0f * c * d;            // segment for im < 1
            D1 = 255.0f * d * a1;           // segment for im > 1
            E1 = Cc - D1;                   // continuity at im = 1
            fast = (D1 <= Cc);              // min-composition valid
        }
    }

    // ---- W (horizontal) resample: unit = (row, 8 out cols); 32*16 = 512 units
    float lmin = 3.0e38f, lmax = -3.0e38f;

#pragma unroll
    for (int it = 0; it < 2; ++it) {
        const int u = tid + it * 256;
        const int h = u & 15;               // output cols 8h..8h+7
        const int r = u >> 4;               // output row (tile-local)

        const float4* p = reinterpret_cast<const float4*>(s_it + r * ITC + 4 * h);
        const float4 qa = p[0], qb = p[1], qc = p[2];
        const float v[12] = { qa.x, qa.y, qa.z, qa.w,
                              qb.x, qb.y, qb.z, qb.w,
                              qc.x, qc.y, qc.z, qc.w };

        float o0 = 0.f, o1 = 0.f, o2 = 0.f, o3 = 0.f;
        float o4 = 0.f, o5 = 0.f, o6 = 0.f, o7 = 0.f;
#pragma unroll
        for (int t = 0; t < 8; ++t) {
            o0 = fmaf(w0[t], v[t],     o0);
            o1 = fmaf(w1[t], v[t + 1], o1);
            o2 = fmaf(w0[t], v[t + 1], o2);
            o3 = fmaf(w1[t], v[t + 2], o3);
            o4 = fmaf(w0[t], v[t + 2], o4);
            o5 = fmaf(w1[t], v[t + 3], o5);
            o6 = fmaf(w0[t], v[t + 3], o6);
            o7 = fmaf(w1[t], v[t + 4], o7);
        }

        if (PASS == 0) {
            float mn0 = fminf(fminf(o0, o1), fminf(o2, o3));
            float mn1 = fminf(fminf(o4, o5), fminf(o6, o7));
            float mx0 = fmaxf(fmaxf(o0, o1), fmaxf(o2, o3));
            float mx1 = fmaxf(fmaxf(o4, o5), fmaxf(o6, o7));
            lmin = fminf(lmin, fminf(mn0, mn1));
            lmax = fmaxf(lmax, fmaxf(mx0, mx1));
        } else {
            const float oo[8] = { o0, o1, o2, o3, o4, o5, o6, o7 };
            float res[8];
#pragma unroll
            for (int q = 0; q < 8; ++q) {
                float y1 = oo[q] * Cc;
                float y2 = fmaf(oo[q], D1, E1);
                float y  = fast ? fminf(y1, y2) : fmaxf(y1, y2);
                res[q] = (float)min(__float2uint_rz(y), 255u);
            }
            float4 q1 = { res[0], res[1], res[2], res[3] };
            float4 q2 = { res[4], res[5], res[6], res[7] };
            size_t o = (size_t)bc * (OUT_H * OUT_W)
                     + (size_t)(oy0 + r) * OUT_W + ox0 + 8 * h;
            *reinterpret_cast<float4*>(out + o)     = q1;
            *reinterpret_cast<float4*>(out + o + 4) = q2;
        }
    }

    if (PASS == 0) {
#pragma unroll
        for (int o = 16; o; o >>= 1) {
            lmin = fminf(lmin, __shfl_xor_sync(0xFFFFFFFFu, lmin, o));
            lmax = fmaxf(lmax, __shfl_xor_sync(0xFFFFFFFFu, lmax, o));
        }
        __shared__ float red[16];
        const int wid = tid >> 5;
        if ((tid & 31) == 0) { red[wid] = lmin; red[8 + wid] = lmax; }
        __syncthreads();
        if (tid == 0) {
            float m0 = red[0], m1 = red[8];
#pragma unroll
            for (int i = 1; i < 8; ++i) {
                m0 = fminf(m0, red[i]);
                m1 = fmaxf(m1, red[8 + i]);
            }
            int lid = blockIdx.x + 8 * (blockIdx.y + 32 * blockIdx.z);
            g_pmin[lid] = m0;
            g_pmax[lid] = m1;
        }
    }
}

extern "C" void kernel_launch(void* const* d_in, const int* in_sizes, int n_in,
                              void* d_out, int out_size) {
    const float* x = (const float*)d_in[0];
    float* out = (float*)d_out;

    dim3 grid(OUT_W / TX, OUT_H / TY, NB * NC);   // 8 x 32 x 96
    k_resize<0><<<grid, 256>>>(x, nullptr);       // resize + per-tile min/max
    k_reduce<<<NB, 256>>>();                      // per-image min/max
    k_resize<1><<<grid, 256>>>(x, out);           // resize + renorm + f32(u8) store
}